// round 3
// baseline (speedup 1.0000x reference)
#include <cuda_runtime.h>
#include <cstddef>

#define DIM 1024
#define HEADS 16
#define DHEAD 64
#define BATCH 4
#define SEQ 2048
#define INNER 1024
#define M_TOTAL (BATCH * SEQ)          // 8192
#define QKV_COLS (3 * INNER)           // 3072
#define SCALE 0.125f                   // 64^-0.5

// Scratch (allocation-free rule: device globals)
__device__ float g_qkv[(size_t)M_TOTAL * QKV_COLS];   // [b*n, 3072]
__device__ float g_att[(size_t)M_TOTAL * INNER];      // [b*n, 1024]

// ---------------------------------------------------------------------------
// SGEMM: C[M,Nc] = A[M,K] @ B[K,Nc] (+ bias). 128x128 tile, BK=8, 256 thr,
// 8x8 per thread, double-buffered smem (1 barrier per k-step).
// ---------------------------------------------------------------------------
template <bool BIAS>
__global__ __launch_bounds__(256)
void sgemm128(const float* __restrict__ A, const float* __restrict__ Bw,
              const float* __restrict__ bias, float* __restrict__ C,
              int M, int Nc, int K)
{
    __shared__ float As[2][8][128];
    __shared__ float Bs[2][8][128];

    const int bx = blockIdx.x;         // N tile
    const int by = blockIdx.y;         // M tile
    const int tid = threadIdx.x;
    const int tr = tid >> 4;           // 0..15
    const int tc = tid & 15;           // 0..15

    const int rowA = by * 128;
    const int colB = bx * 128;

    const int aRow = tid >> 1;         // 0..127
    const int aK4  = (tid & 1) * 4;    // 0 or 4
    const int bK   = tid >> 5;         // 0..7
    const int bN4  = (tid & 31) * 4;   // 0..124

    float acc[8][8];
    #pragma unroll
    for (int i = 0; i < 8; i++)
        #pragma unroll
        for (int j = 0; j < 8; j++) acc[i][j] = 0.0f;

    // Prologue: load k-tile 0 into buffer 0
    {
        float4 av = *(const float4*)&A[(size_t)(rowA + aRow) * K + aK4];
        As[0][aK4 + 0][aRow] = av.x;
        As[0][aK4 + 1][aRow] = av.y;
        As[0][aK4 + 2][aRow] = av.z;
        As[0][aK4 + 3][aRow] = av.w;
        *(float4*)&Bs[0][bK][bN4] =
            *(const float4*)&Bw[(size_t)bK * Nc + colB + bN4];
    }
    __syncthreads();

    int buf = 0;
    for (int k0 = 0; k0 < K; k0 += 8) {
        // Prefetch next k-tile into registers (overlaps with compute below)
        float4 avn, bvn;
        const bool more = (k0 + 8 < K);
        if (more) {
            avn = *(const float4*)&A[(size_t)(rowA + aRow) * K + k0 + 8 + aK4];
            bvn = *(const float4*)&Bw[(size_t)(k0 + 8 + bK) * Nc + colB + bN4];
        }

        // Compute on current buffer
        #pragma unroll
        for (int k = 0; k < 8; k++) {
            float4 a0 = *(float4*)&As[buf][k][tr * 8];
            float4 a1 = *(float4*)&As[buf][k][tr * 8 + 4];
            float4 b0 = *(float4*)&Bs[buf][k][tc * 8];
            float4 b1 = *(float4*)&Bs[buf][k][tc * 8 + 4];
            float a[8] = {a0.x, a0.y, a0.z, a0.w, a1.x, a1.y, a1.z, a1.w};
            float b[8] = {b0.x, b0.y, b0.z, b0.w, b1.x, b1.y, b1.z, b1.w};
            #pragma unroll
            for (int i = 0; i < 8; i++)
                #pragma unroll
                for (int j = 0; j < 8; j++)
                    acc[i][j] += a[i] * b[j];
        }

        // Store prefetched tile into the other buffer
        if (more) {
            As[buf ^ 1][aK4 + 0][aRow] = avn.x;
            As[buf ^ 1][aK4 + 1][aRow] = avn.y;
            As[buf ^ 1][aK4 + 2][aRow] = avn.z;
            As[buf ^ 1][aK4 + 3][aRow] = avn.w;
            *(float4*)&Bs[buf ^ 1][bK][bN4] = bvn;
        }
        __syncthreads();
        buf ^= 1;
    }

    #pragma unroll
    for (int i = 0; i < 8; i++) {
        const int r = rowA + tr * 8 + i;
        #pragma unroll
        for (int j4 = 0; j4 < 8; j4 += 4) {
            const int c = colB + tc * 8 + j4;
            float4 v;
            v.x = acc[i][j4 + 0];
            v.y = acc[i][j4 + 1];
            v.z = acc[i][j4 + 2];
            v.w = acc[i][j4 + 3];
            if (BIAS) {
                v.x += bias[c + 0];
                v.y += bias[c + 1];
                v.z += bias[c + 2];
                v.w += bias[c + 3];
            }
            *(float4*)&C[(size_t)r * Nc + c] = v;
        }
    }
}

// ---------------------------------------------------------------------------
// Flash-style causal attention. One CTA = (b, h, 64-row Q block).
// Online softmax kept entirely in registers: row r = tr*4+i is owned by the
// 16 threads sharing tr (contiguous 16-lane group within a warp-half), so
// row reductions are 4-step __shfl_xor (1,2,4,8) and m/l/alpha are
// thread-local, replicated consistently across the group.
// smem: Q[64][64], K[64][65] (padded), V[64][64], P[64][64].
// ---------------------------------------------------------------------------
__global__ __launch_bounds__(256)
void attn_kernel()
{
    extern __shared__ float sm[];
    float* Qs = sm;                 // 64*64
    float* Ks = Qs + 64 * 64;       // 64*65 (padded rows)
    float* Vs = Ks + 64 * 65;       // 64*64
    float* Ps = Vs + 64 * 64;       // 64*64

    const int qb = blockIdx.x;              // 0..31
    const int bh = blockIdx.y;              // 0..63
    const int bb = bh >> 4;
    const int h  = bh & 15;

    const int tid = threadIdx.x;
    const int tr = tid >> 4;                // 0..15
    const int tc = tid & 15;                // 0..15

    const size_t rowbase = (size_t)bb * SEQ * QKV_COLS;
    const int qcol = h * DHEAD;

    // Load Q tile (rows qb*64..+63)
    for (int idx = tid; idx < 64 * 16; idx += 256) {
        const int r  = idx >> 4;
        const int c4 = (idx & 15) * 4;
        *(float4*)&Qs[r * 64 + c4] =
            *(const float4*)&g_qkv[rowbase + (size_t)(qb * 64 + r) * QKV_COLS + qcol + c4];
    }

    float o[4][4];
    float m_r[4], l_r[4];
    #pragma unroll
    for (int i = 0; i < 4; i++) {
        m_r[i] = -1e30f;
        l_r[i] = 0.0f;
        #pragma unroll
        for (int j = 0; j < 4; j++) o[i][j] = 0.0f;
    }

    for (int jb = 0; jb <= qb; jb++) {
        __syncthreads();   // protect K/V/P from previous iteration's readers

        // Load K (padded, scalar stores) and V (float4)
        for (int idx = tid; idx < 64 * 16; idx += 256) {
            const int r  = idx >> 4;
            const int c4 = (idx & 15) * 4;
            const size_t rb = rowbase + (size_t)(jb * 64 + r) * QKV_COLS;
            float4 kv = *(const float4*)&g_qkv[rb + INNER + qcol + c4];
            Ks[r * 65 + c4 + 0] = kv.x;
            Ks[r * 65 + c4 + 1] = kv.y;
            Ks[r * 65 + c4 + 2] = kv.z;
            Ks[r * 65 + c4 + 3] = kv.w;
            *(float4*)&Vs[r * 64 + c4] =
                *(const float4*)&g_qkv[rb + 2 * INNER + qcol + c4];
        }
        __syncthreads();

        // S = Q @ K^T   (4x4 per thread)
        float s[4][4];
        #pragma unroll
        for (int i = 0; i < 4; i++)
            #pragma unroll
            for (int j = 0; j < 4; j++) s[i][j] = 0.0f;

        #pragma unroll 4
        for (int d = 0; d < 64; d++) {
            float q[4], kk[4];
            #pragma unroll
            for (int i = 0; i < 4; i++) q[i]  = Qs[(tr * 4 + i) * 64 + d];
            #pragma unroll
            for (int j = 0; j < 4; j++) kk[j] = Ks[(tc * 4 + j) * 65 + d];
            #pragma unroll
            for (int i = 0; i < 4; i++)
                #pragma unroll
                for (int j = 0; j < 4; j++)
                    s[i][j] += q[i] * kk[j];
        }

        // Scale + causal mask (in registers)
        const bool diag = (jb == qb);
        #pragma unroll
        for (int i = 0; i < 4; i++) {
            const int row = tr * 4 + i;
            #pragma unroll
            for (int j = 0; j < 4; j++) {
                const int col = tc * 4 + j;
                s[i][j] *= SCALE;
                if (diag && col > row) s[i][j] = -1e9f;
            }
        }

        // Online softmax fully in registers. The 16 threads owning a row are
        // lanes (tr&1)*16 + 0..15 of one warp; xor offsets 1,2,4,8 reduce
        // across exactly that group.
        #pragma unroll
        for (int i = 0; i < 4; i++) {
            float mx = fmaxf(fmaxf(s[i][0], s[i][1]), fmaxf(s[i][2], s[i][3]));
            #pragma unroll
            for (int off = 8; off > 0; off >>= 1)
                mx = fmaxf(mx, __shfl_xor_sync(0xffffffffu, mx, off));
            const float m_new = fmaxf(m_r[i], mx);
            float p[4], psum = 0.0f;
            #pragma unroll
            for (int j = 0; j < 4; j++) {
                p[j] = __expf(s[i][j] - m_new);
                psum += p[j];
            }
            #pragma unroll
            for (int off = 8; off > 0; off >>= 1)
                psum += __shfl_xor_sync(0xffffffffu, psum, off);
            const float alpha = __expf(m_r[i] - m_new);
            l_r[i] = l_r[i] * alpha + psum;
            m_r[i] = m_new;
            // rescale O, stash P to smem for the k-contraction
            #pragma unroll
            for (int j = 0; j < 4; j++) {
                o[i][j] *= alpha;
                Ps[(tr * 4 + i) * 64 + tc * 4 + j] = p[j];
            }
        }
        __syncthreads();

        // O += P @ V
        #pragma unroll 4
        for (int k = 0; k < 64; k++) {
            float4 vv = *(float4*)&Vs[k * 64 + tc * 4];
            #pragma unroll
            for (int i = 0; i < 4; i++) {
                const float p = Ps[(tr * 4 + i) * 64 + k];
                o[i][0] += p * vv.x;
                o[i][1] += p * vv.y;
                o[i][2] += p * vv.z;
                o[i][3] += p * vv.w;
            }
        }
    }

    // Normalize + write to g_att [b*n, 1024]
    #pragma unroll
    for (int i = 0; i < 4; i++) {
        const int row = tr * 4 + i;
        const float inv = 1.0f / l_r[i];
        float4 v;
        v.x = o[i][0] * inv;
        v.y = o[i][1] * inv;
        v.z = o[i][2] * inv;
        v.w = o[i][3] * inv;
        const size_t n_idx = (size_t)bb * SEQ + qb * 64 + row;
        *(float4*)&g_att[n_idx * INNER + qcol + tc * 4] = v;
    }
}

// ---------------------------------------------------------------------------
extern "C" void kernel_launch(void* const* d_in, const int* in_sizes, int n_in,
                              void* d_out, int out_size)
{
    const float* x     = (const float*)d_in[0];  // [4,2048,1024]
    const float* w_qkv = (const float*)d_in[1];  // [1024,3072]
    const float* w_out = (const float*)d_in[2];  // [1024,1024]
    const float* b_out = (const float*)d_in[3];  // [1024]
    float* out = (float*)d_out;                  // [4,2048,1024]

    float* qkv_ptr = nullptr;
    float* att_ptr = nullptr;
    cudaGetSymbolAddress((void**)&qkv_ptr, g_qkv);
    cudaGetSymbolAddress((void**)&att_ptr, g_att);

    // 1) QKV projection: [8192,1024] @ [1024,3072]
    {
        dim3 grid(QKV_COLS / 128, M_TOTAL / 128);   // (24, 64)
        sgemm128<false><<<grid, 256>>>(x, w_qkv, nullptr, qkv_ptr,
                                       M_TOTAL, QKV_COLS, DIM);
    }

    // 2) Causal flash attention
    {
        const int smem_bytes = (64 * 64 + 64 * 65 + 64 * 64 + 64 * 64) * 4; // 65792
        cudaFuncSetAttribute(attn_kernel,
                             cudaFuncAttributeMaxDynamicSharedMemorySize,
                             smem_bytes);
        dim3 grid(SEQ / 64, BATCH * HEADS);         // (32, 64)
        attn_kernel<<<grid, 256, smem_bytes>>>();
    }

    // 3) Output projection with bias: [8192,1024] @ [1024,1024] + b
    {
        dim3 grid(DIM / 128, M_TOTAL / 128);        // (8, 64)
        sgemm128<true><<<grid, 256>>>(att_ptr, w_out, b_out, out,
                                      M_TOTAL, DIM, INNER);
    }
}

// round 4
// speedup vs baseline: 1.5555x; 1.5555x over previous
#include <cuda_runtime.h>
#include <cstddef>
#include <cstdint>

#define DIM 1024
#define HEADS 16
#define DHEAD 64
#define BATCH 4
#define SEQ 2048
#define INNER 1024
#define M_TOTAL (BATCH * SEQ)          // 8192
#define QKV_COLS (3 * INNER)           // 3072
#define SCALE 0.125f                   // 64^-0.5

// Scratch (allocation-free rule: device globals)
__device__ float g_qkv[(size_t)M_TOTAL * QKV_COLS];   // [b*n, 3072]
__device__ float g_att[(size_t)M_TOTAL * INNER];      // [b*n, 1024]

// ---------------------------------------------------------------------------
// tf32 helpers
// ---------------------------------------------------------------------------
__device__ __forceinline__ unsigned f2tf32(float f) {
    unsigned u;
    asm("cvt.rna.tf32.f32 %0, %1;" : "=r"(u) : "f"(f));
    return u;
}

__device__ __forceinline__ void mma_tf32(float& d0, float& d1, float& d2, float& d3,
                                         unsigned a0, unsigned a1, unsigned a2, unsigned a3,
                                         unsigned b0, unsigned b1)
{
    asm volatile(
        "mma.sync.aligned.m16n8k8.row.col.f32.tf32.tf32.f32 "
        "{%0,%1,%2,%3}, {%4,%5,%6,%7}, {%8,%9}, {%0,%1,%2,%3};"
        : "+f"(d0), "+f"(d1), "+f"(d2), "+f"(d3)
        : "r"(a0), "r"(a1), "r"(a2), "r"(a3), "r"(b0), "r"(b1));
}

// ---------------------------------------------------------------------------
// tf32 tensor-core GEMM: C[M,Nc] = A[M,K] @ B[K,Nc] (+ bias)
// 128x128 CTA tile, BK=16, 256 threads (8 warps, 2x4 grid, warp = 64x32).
// smem K-major with rows padded to 136 words -> bank = (8k + r) mod 32,
// a full permutation for every fragment gather (conflict-free).
// Double-buffered with register prefetch: 1 barrier per BK.
// ---------------------------------------------------------------------------
#define LDPAD 136

template <bool BIAS>
__global__ __launch_bounds__(256)
void tgemm128(const float* __restrict__ A, const float* __restrict__ Bw,
              const float* __restrict__ bias, float* __restrict__ C,
              int M, int Nc, int K)
{
    __shared__ unsigned As[2][16][LDPAD];
    __shared__ unsigned Bs[2][16][LDPAD];

    const int bx = blockIdx.x;         // N tile
    const int by = blockIdx.y;         // M tile
    const int tid = threadIdx.x;
    const int warp = tid >> 5;
    const int lane = tid & 31;
    const int quad = lane >> 2;        // 0..7
    const int tig  = lane & 3;         // 0..3
    const int warp_m = warp >> 2;      // 0..1
    const int warp_n = warp & 3;       // 0..3

    const int rowA = by * 128;
    const int colB = bx * 128;

    // A load mapping: 128 rows x 4 chunks(4k) = 512 float4; thread does 2.
    const int aRow0  = tid >> 2;        // 0..63 (second load +64)
    const int aChunk = (tid & 3) * 4;   // k offset 0,4,8,12
    // B load mapping: 16 k-rows x 32 chunks(4n) = 512 float4; thread does 2.
    const int bK0 = tid >> 5;           // 0..7 (second load +8)
    const int bN4 = (lane) * 4;         // 0..124

    float acc[4][4][4];
    #pragma unroll
    for (int mt = 0; mt < 4; mt++)
        #pragma unroll
        for (int nt = 0; nt < 4; nt++)
            #pragma unroll
            for (int r = 0; r < 4; r++) acc[mt][nt][r] = 0.0f;

    // ---- prologue: k-tile 0 into buffer 0 ----
    {
        float4 a0 = *(const float4*)&A[(size_t)(rowA + aRow0) * K + aChunk];
        float4 a1 = *(const float4*)&A[(size_t)(rowA + aRow0 + 64) * K + aChunk];
        As[0][aChunk + 0][aRow0] = f2tf32(a0.x);
        As[0][aChunk + 1][aRow0] = f2tf32(a0.y);
        As[0][aChunk + 2][aRow0] = f2tf32(a0.z);
        As[0][aChunk + 3][aRow0] = f2tf32(a0.w);
        As[0][aChunk + 0][aRow0 + 64] = f2tf32(a1.x);
        As[0][aChunk + 1][aRow0 + 64] = f2tf32(a1.y);
        As[0][aChunk + 2][aRow0 + 64] = f2tf32(a1.z);
        As[0][aChunk + 3][aRow0 + 64] = f2tf32(a1.w);

        float4 b0 = *(const float4*)&Bw[(size_t)bK0 * Nc + colB + bN4];
        float4 b1 = *(const float4*)&Bw[(size_t)(bK0 + 8) * Nc + colB + bN4];
        uint4 u0 = {f2tf32(b0.x), f2tf32(b0.y), f2tf32(b0.z), f2tf32(b0.w)};
        uint4 u1 = {f2tf32(b1.x), f2tf32(b1.y), f2tf32(b1.z), f2tf32(b1.w)};
        *(uint4*)&Bs[0][bK0][bN4] = u0;
        *(uint4*)&Bs[0][bK0 + 8][bN4] = u1;
    }
    __syncthreads();

    int buf = 0;
    for (int k0 = 0; k0 < K; k0 += 16) {
        // prefetch next BK into registers
        float4 pa0, pa1, pb0, pb1;
        const bool more = (k0 + 16 < K);
        if (more) {
            pa0 = *(const float4*)&A[(size_t)(rowA + aRow0) * K + k0 + 16 + aChunk];
            pa1 = *(const float4*)&A[(size_t)(rowA + aRow0 + 64) * K + k0 + 16 + aChunk];
            pb0 = *(const float4*)&Bw[(size_t)(k0 + 16 + bK0) * Nc + colB + bN4];
            pb1 = *(const float4*)&Bw[(size_t)(k0 + 16 + bK0 + 8) * Nc + colB + bN4];
        }

        // compute on current buffer: two k8 steps
        #pragma unroll
        for (int ks = 0; ks < 2; ks++) {
            const int kb = ks * 8;
            unsigned af[4][4];
            #pragma unroll
            for (int mt = 0; mt < 4; mt++) {
                const int rb = warp_m * 64 + mt * 16 + quad;
                af[mt][0] = As[buf][kb + tig][rb];
                af[mt][1] = As[buf][kb + tig][rb + 8];
                af[mt][2] = As[buf][kb + tig + 4][rb];
                af[mt][3] = As[buf][kb + tig + 4][rb + 8];
            }
            unsigned bf[4][2];
            #pragma unroll
            for (int nt = 0; nt < 4; nt++) {
                const int nb = warp_n * 32 + nt * 8 + quad;
                bf[nt][0] = Bs[buf][kb + tig][nb];
                bf[nt][1] = Bs[buf][kb + tig + 4][nb];
            }
            #pragma unroll
            for (int mt = 0; mt < 4; mt++)
                #pragma unroll
                for (int nt = 0; nt < 4; nt++)
                    mma_tf32(acc[mt][nt][0], acc[mt][nt][1],
                             acc[mt][nt][2], acc[mt][nt][3],
                             af[mt][0], af[mt][1], af[mt][2], af[mt][3],
                             bf[nt][0], bf[nt][1]);
        }

        // store prefetched tile into the other buffer
        if (more) {
            const int nb = buf ^ 1;
            As[nb][aChunk + 0][aRow0] = f2tf32(pa0.x);
            As[nb][aChunk + 1][aRow0] = f2tf32(pa0.y);
            As[nb][aChunk + 2][aRow0] = f2tf32(pa0.z);
            As[nb][aChunk + 3][aRow0] = f2tf32(pa0.w);
            As[nb][aChunk + 0][aRow0 + 64] = f2tf32(pa1.x);
            As[nb][aChunk + 1][aRow0 + 64] = f2tf32(pa1.y);
            As[nb][aChunk + 2][aRow0 + 64] = f2tf32(pa1.z);
            As[nb][aChunk + 3][aRow0 + 64] = f2tf32(pa1.w);
            uint4 u0 = {f2tf32(pb0.x), f2tf32(pb0.y), f2tf32(pb0.z), f2tf32(pb0.w)};
            uint4 u1 = {f2tf32(pb1.x), f2tf32(pb1.y), f2tf32(pb1.z), f2tf32(pb1.w)};
            *(uint4*)&Bs[nb][bK0][bN4] = u0;
            *(uint4*)&Bs[nb][bK0 + 8][bN4] = u1;
        }
        __syncthreads();
        buf ^= 1;
    }

    // epilogue: C fragment layout c0,c1 = (row, 2*tig), (row, 2*tig+1);
    //           c2,c3 = (row+8, ...)
    #pragma unroll
    for (int mt = 0; mt < 4; mt++) {
        const int r0 = rowA + warp_m * 64 + mt * 16 + quad;
        #pragma unroll
        for (int nt = 0; nt < 4; nt++) {
            const int c = colB + warp_n * 32 + nt * 8 + 2 * tig;
            float bx0 = 0.f, bx1 = 0.f;
            if (BIAS) { bx0 = bias[c]; bx1 = bias[c + 1]; }
            float2 v0 = {acc[mt][nt][0] + bx0, acc[mt][nt][1] + bx1};
            float2 v1 = {acc[mt][nt][2] + bx0, acc[mt][nt][3] + bx1};
            *(float2*)&C[(size_t)r0 * Nc + c] = v0;
            *(float2*)&C[(size_t)(r0 + 8) * Nc + c] = v1;
        }
    }
}

// ---------------------------------------------------------------------------
// Flash-style causal attention (unchanged from round 3 — passing, fp32).
// One CTA = (b, h, 64-row Q block). Register-resident online softmax.
// ---------------------------------------------------------------------------
__global__ __launch_bounds__(256)
void attn_kernel()
{
    extern __shared__ float sm[];
    float* Qs = sm;                 // 64*64
    float* Ks = Qs + 64 * 64;       // 64*65 (padded rows)
    float* Vs = Ks + 64 * 65;       // 64*64
    float* Ps = Vs + 64 * 64;       // 64*64

    const int qb = blockIdx.x;              // 0..31
    const int bh = blockIdx.y;              // 0..63
    const int bb = bh >> 4;
    const int h  = bh & 15;

    const int tid = threadIdx.x;
    const int tr = tid >> 4;                // 0..15
    const int tc = tid & 15;                // 0..15

    const size_t rowbase = (size_t)bb * SEQ * QKV_COLS;
    const int qcol = h * DHEAD;

    // Load Q tile (rows qb*64..+63)
    for (int idx = tid; idx < 64 * 16; idx += 256) {
        const int r  = idx >> 4;
        const int c4 = (idx & 15) * 4;
        *(float4*)&Qs[r * 64 + c4] =
            *(const float4*)&g_qkv[rowbase + (size_t)(qb * 64 + r) * QKV_COLS + qcol + c4];
    }

    float o[4][4];
    float m_r[4], l_r[4];
    #pragma unroll
    for (int i = 0; i < 4; i++) {
        m_r[i] = -1e30f;
        l_r[i] = 0.0f;
        #pragma unroll
        for (int j = 0; j < 4; j++) o[i][j] = 0.0f;
    }

    for (int jb = 0; jb <= qb; jb++) {
        __syncthreads();   // protect K/V/P from previous iteration's readers

        // Load K (padded, scalar stores) and V (float4)
        for (int idx = tid; idx < 64 * 16; idx += 256) {
            const int r  = idx >> 4;
            const int c4 = (idx & 15) * 4;
            const size_t rb = rowbase + (size_t)(jb * 64 + r) * QKV_COLS;
            float4 kv = *(const float4*)&g_qkv[rb + INNER + qcol + c4];
            Ks[r * 65 + c4 + 0] = kv.x;
            Ks[r * 65 + c4 + 1] = kv.y;
            Ks[r * 65 + c4 + 2] = kv.z;
            Ks[r * 65 + c4 + 3] = kv.w;
            *(float4*)&Vs[r * 64 + c4] =
                *(const float4*)&g_qkv[rb + 2 * INNER + qcol + c4];
        }
        __syncthreads();

        // S = Q @ K^T   (4x4 per thread)
        float s[4][4];
        #pragma unroll
        for (int i = 0; i < 4; i++)
            #pragma unroll
            for (int j = 0; j < 4; j++) s[i][j] = 0.0f;

        #pragma unroll 4
        for (int d = 0; d < 64; d++) {
            float q[4], kk[4];
            #pragma unroll
            for (int i = 0; i < 4; i++) q[i]  = Qs[(tr * 4 + i) * 64 + d];
            #pragma unroll
            for (int j = 0; j < 4; j++) kk[j] = Ks[(tc * 4 + j) * 65 + d];
            #pragma unroll
            for (int i = 0; i < 4; i++)
                #pragma unroll
                for (int j = 0; j < 4; j++)
                    s[i][j] += q[i] * kk[j];
        }

        // Scale + causal mask (in registers)
        const bool diag = (jb == qb);
        #pragma unroll
        for (int i = 0; i < 4; i++) {
            const int row = tr * 4 + i;
            #pragma unroll
            for (int j = 0; j < 4; j++) {
                const int col = tc * 4 + j;
                s[i][j] *= SCALE;
                if (diag && col > row) s[i][j] = -1e9f;
            }
        }

        // Online softmax fully in registers (16-thread row groups, xor 1..8)
        #pragma unroll
        for (int i = 0; i < 4; i++) {
            float mx = fmaxf(fmaxf(s[i][0], s[i][1]), fmaxf(s[i][2], s[i][3]));
            #pragma unroll
            for (int off = 8; off > 0; off >>= 1)
                mx = fmaxf(mx, __shfl_xor_sync(0xffffffffu, mx, off));
            const float m_new = fmaxf(m_r[i], mx);
            float p[4], psum = 0.0f;
            #pragma unroll
            for (int j = 0; j < 4; j++) {
                p[j] = __expf(s[i][j] - m_new);
                psum += p[j];
            }
            #pragma unroll
            for (int off = 8; off > 0; off >>= 1)
                psum += __shfl_xor_sync(0xffffffffu, psum, off);
            const float alpha = __expf(m_r[i] - m_new);
            l_r[i] = l_r[i] * alpha + psum;
            m_r[i] = m_new;
            #pragma unroll
            for (int j = 0; j < 4; j++) {
                o[i][j] *= alpha;
                Ps[(tr * 4 + i) * 64 + tc * 4 + j] = p[j];
            }
        }
        __syncthreads();

        // O += P @ V
        #pragma unroll 4
        for (int k = 0; k < 64; k++) {
            float4 vv = *(float4*)&Vs[k * 64 + tc * 4];
            #pragma unroll
            for (int i = 0; i < 4; i++) {
                const float p = Ps[(tr * 4 + i) * 64 + k];
                o[i][0] += p * vv.x;
                o[i][1] += p * vv.y;
                o[i][2] += p * vv.z;
                o[i][3] += p * vv.w;
            }
        }
    }

    // Normalize + write to g_att [b*n, 1024]
    #pragma unroll
    for (int i = 0; i < 4; i++) {
        const int row = tr * 4 + i;
        const float inv = 1.0f / l_r[i];
        float4 v;
        v.x = o[i][0] * inv;
        v.y = o[i][1] * inv;
        v.z = o[i][2] * inv;
        v.w = o[i][3] * inv;
        const size_t n_idx = (size_t)bb * SEQ + qb * 64 + row;
        *(float4*)&g_att[n_idx * INNER + qcol + tc * 4] = v;
    }
}

// ---------------------------------------------------------------------------
extern "C" void kernel_launch(void* const* d_in, const int* in_sizes, int n_in,
                              void* d_out, int out_size)
{
    const float* x     = (const float*)d_in[0];  // [4,2048,1024]
    const float* w_qkv = (const float*)d_in[1];  // [1024,3072]
    const float* w_out = (const float*)d_in[2];  // [1024,1024]
    const float* b_out = (const float*)d_in[3];  // [1024]
    float* out = (float*)d_out;                  // [4,2048,1024]

    float* qkv_ptr = nullptr;
    float* att_ptr = nullptr;
    cudaGetSymbolAddress((void**)&qkv_ptr, g_qkv);
    cudaGetSymbolAddress((void**)&att_ptr, g_att);

    // 1) QKV projection: [8192,1024] @ [1024,3072]  (tf32 tensor cores)
    {
        dim3 grid(QKV_COLS / 128, M_TOTAL / 128);   // (24, 64)
        tgemm128<false><<<grid, 256>>>(x, w_qkv, nullptr, qkv_ptr,
                                       M_TOTAL, QKV_COLS, DIM);
    }

    // 2) Causal flash attention (fp32)
    {
        const int smem_bytes = (64 * 64 + 64 * 65 + 64 * 64 + 64 * 64) * 4; // 65792
        cudaFuncSetAttribute(attn_kernel,
                             cudaFuncAttributeMaxDynamicSharedMemorySize,
                             smem_bytes);
        dim3 grid(SEQ / 64, BATCH * HEADS);         // (32, 64)
        attn_kernel<<<grid, 256, smem_bytes>>>();
    }

    // 3) Output projection with bias: [8192,1024] @ [1024,1024] + b (tf32)
    {
        dim3 grid(DIM / 128, M_TOTAL / 128);        // (8, 64)
        tgemm128<true><<<grid, 256>>>(att_ptr, w_out, b_out, out,
                                      M_TOTAL, DIM, INNER);
    }
}

// round 5
// speedup vs baseline: 1.8652x; 1.1991x over previous
#include <cuda_runtime.h>
#include <cstddef>
#include <cstdint>

#define DIM 1024
#define HEADS 16
#define DHEAD 64
#define BATCH 4
#define SEQ 2048
#define INNER 1024
#define M_TOTAL (BATCH * SEQ)          // 8192
#define QKV_COLS (3 * INNER)           // 3072
#define SCALE 0.125f                   // 64^-0.5

// Scratch (allocation-free rule: device globals)
__device__ float g_qkv[(size_t)M_TOTAL * QKV_COLS];   // [b*n, 3072]
__device__ float g_att[(size_t)M_TOTAL * INNER];      // [b*n, 1024]

// ---------------------------------------------------------------------------
// tf32 helpers
// ---------------------------------------------------------------------------
__device__ __forceinline__ unsigned f2tf32(float f) {
    unsigned u;
    asm("cvt.rna.tf32.f32 %0, %1;" : "=r"(u) : "f"(f));
    return u;
}

__device__ __forceinline__ void mma_tf32(float& d0, float& d1, float& d2, float& d3,
                                         unsigned a0, unsigned a1, unsigned a2, unsigned a3,
                                         unsigned b0, unsigned b1)
{
    asm volatile(
        "mma.sync.aligned.m16n8k8.row.col.f32.tf32.tf32.f32 "
        "{%0,%1,%2,%3}, {%4,%5,%6,%7}, {%8,%9}, {%0,%1,%2,%3};"
        : "+f"(d0), "+f"(d1), "+f"(d2), "+f"(d3)
        : "r"(a0), "r"(a1), "r"(a2), "r"(a3), "r"(b0), "r"(b1));
}

// ---------------------------------------------------------------------------
// tf32 tensor-core GEMM (unchanged from round 4 — passing).
// ---------------------------------------------------------------------------
#define LDPAD 136

template <bool BIAS>
__global__ __launch_bounds__(256)
void tgemm128(const float* __restrict__ A, const float* __restrict__ Bw,
              const float* __restrict__ bias, float* __restrict__ C,
              int M, int Nc, int K)
{
    __shared__ unsigned As[2][16][LDPAD];
    __shared__ unsigned Bs[2][16][LDPAD];

    const int bx = blockIdx.x;
    const int by = blockIdx.y;
    const int tid = threadIdx.x;
    const int warp = tid >> 5;
    const int lane = tid & 31;
    const int quad = lane >> 2;
    const int tig  = lane & 3;
    const int warp_m = warp >> 2;
    const int warp_n = warp & 3;

    const int rowA = by * 128;
    const int colB = bx * 128;

    const int aRow0  = tid >> 2;
    const int aChunk = (tid & 3) * 4;
    const int bK0 = tid >> 5;
    const int bN4 = (lane) * 4;

    float acc[4][4][4];
    #pragma unroll
    for (int mt = 0; mt < 4; mt++)
        #pragma unroll
        for (int nt = 0; nt < 4; nt++)
            #pragma unroll
            for (int r = 0; r < 4; r++) acc[mt][nt][r] = 0.0f;

    {
        float4 a0 = *(const float4*)&A[(size_t)(rowA + aRow0) * K + aChunk];
        float4 a1 = *(const float4*)&A[(size_t)(rowA + aRow0 + 64) * K + aChunk];
        As[0][aChunk + 0][aRow0] = f2tf32(a0.x);
        As[0][aChunk + 1][aRow0] = f2tf32(a0.y);
        As[0][aChunk + 2][aRow0] = f2tf32(a0.z);
        As[0][aChunk + 3][aRow0] = f2tf32(a0.w);
        As[0][aChunk + 0][aRow0 + 64] = f2tf32(a1.x);
        As[0][aChunk + 1][aRow0 + 64] = f2tf32(a1.y);
        As[0][aChunk + 2][aRow0 + 64] = f2tf32(a1.z);
        As[0][aChunk + 3][aRow0 + 64] = f2tf32(a1.w);

        float4 b0 = *(const float4*)&Bw[(size_t)bK0 * Nc + colB + bN4];
        float4 b1 = *(const float4*)&Bw[(size_t)(bK0 + 8) * Nc + colB + bN4];
        uint4 u0 = {f2tf32(b0.x), f2tf32(b0.y), f2tf32(b0.z), f2tf32(b0.w)};
        uint4 u1 = {f2tf32(b1.x), f2tf32(b1.y), f2tf32(b1.z), f2tf32(b1.w)};
        *(uint4*)&Bs[0][bK0][bN4] = u0;
        *(uint4*)&Bs[0][bK0 + 8][bN4] = u1;
    }
    __syncthreads();

    int buf = 0;
    for (int k0 = 0; k0 < K; k0 += 16) {
        float4 pa0, pa1, pb0, pb1;
        const bool more = (k0 + 16 < K);
        if (more) {
            pa0 = *(const float4*)&A[(size_t)(rowA + aRow0) * K + k0 + 16 + aChunk];
            pa1 = *(const float4*)&A[(size_t)(rowA + aRow0 + 64) * K + k0 + 16 + aChunk];
            pb0 = *(const float4*)&Bw[(size_t)(k0 + 16 + bK0) * Nc + colB + bN4];
            pb1 = *(const float4*)&Bw[(size_t)(k0 + 16 + bK0 + 8) * Nc + colB + bN4];
        }

        #pragma unroll
        for (int ks = 0; ks < 2; ks++) {
            const int kb = ks * 8;
            unsigned af[4][4];
            #pragma unroll
            for (int mt = 0; mt < 4; mt++) {
                const int rb = warp_m * 64 + mt * 16 + quad;
                af[mt][0] = As[buf][kb + tig][rb];
                af[mt][1] = As[buf][kb + tig][rb + 8];
                af[mt][2] = As[buf][kb + tig + 4][rb];
                af[mt][3] = As[buf][kb + tig + 4][rb + 8];
            }
            unsigned bf[4][2];
            #pragma unroll
            for (int nt = 0; nt < 4; nt++) {
                const int nb = warp_n * 32 + nt * 8 + quad;
                bf[nt][0] = Bs[buf][kb + tig][nb];
                bf[nt][1] = Bs[buf][kb + tig + 4][nb];
            }
            #pragma unroll
            for (int mt = 0; mt < 4; mt++)
                #pragma unroll
                for (int nt = 0; nt < 4; nt++)
                    mma_tf32(acc[mt][nt][0], acc[mt][nt][1],
                             acc[mt][nt][2], acc[mt][nt][3],
                             af[mt][0], af[mt][1], af[mt][2], af[mt][3],
                             bf[nt][0], bf[nt][1]);
        }

        if (more) {
            const int nb = buf ^ 1;
            As[nb][aChunk + 0][aRow0] = f2tf32(pa0.x);
            As[nb][aChunk + 1][aRow0] = f2tf32(pa0.y);
            As[nb][aChunk + 2][aRow0] = f2tf32(pa0.z);
            As[nb][aChunk + 3][aRow0] = f2tf32(pa0.w);
            As[nb][aChunk + 0][aRow0 + 64] = f2tf32(pa1.x);
            As[nb][aChunk + 1][aRow0 + 64] = f2tf32(pa1.y);
            As[nb][aChunk + 2][aRow0 + 64] = f2tf32(pa1.z);
            As[nb][aChunk + 3][aRow0 + 64] = f2tf32(pa1.w);
            uint4 u0 = {f2tf32(pb0.x), f2tf32(pb0.y), f2tf32(pb0.z), f2tf32(pb0.w)};
            uint4 u1 = {f2tf32(pb1.x), f2tf32(pb1.y), f2tf32(pb1.z), f2tf32(pb1.w)};
            *(uint4*)&Bs[nb][bK0][bN4] = u0;
            *(uint4*)&Bs[nb][bK0 + 8][bN4] = u1;
        }
        __syncthreads();
        buf ^= 1;
    }

    #pragma unroll
    for (int mt = 0; mt < 4; mt++) {
        const int r0 = rowA + warp_m * 64 + mt * 16 + quad;
        #pragma unroll
        for (int nt = 0; nt < 4; nt++) {
            const int c = colB + warp_n * 32 + nt * 8 + 2 * tig;
            float bx0 = 0.f, bx1 = 0.f;
            if (BIAS) { bx0 = bias[c]; bx1 = bias[c + 1]; }
            float2 v0 = {acc[mt][nt][0] + bx0, acc[mt][nt][1] + bx1};
            float2 v1 = {acc[mt][nt][2] + bx0, acc[mt][nt][3] + bx1};
            *(float2*)&C[(size_t)r0 * Nc + c] = v0;
            *(float2*)&C[(size_t)(r0 + 8) * Nc + c] = v1;
        }
    }
}

// ---------------------------------------------------------------------------
// Tensor-core causal flash attention.
// CTA = (b, h, 64-row Q block), 4 warps; warp owns 16 rows x full 64 cols,
// so softmax row stats live in registers (reduce over 4-lane quad groups).
// QK^T and P@V via mma.m16n8k8.tf32. SCALE folded into Q conversion (2^-3,
// lossless). P is warp-private: only __syncwarp between P store and P@V.
// Strides: Q/K/P rows = 68 words (gather bank = 4*quad+tig, conflict-free),
// V rows = 72 words (gather bank = 8*tig+quad, conflict-free).
// ---------------------------------------------------------------------------
#define ALD 68
#define VLD 72

__global__ __launch_bounds__(128)
void attn_mma_kernel()
{
    extern __shared__ unsigned smu[];
    unsigned* Qs = smu;                 // 64*68
    unsigned* Ks = Qs + 64 * ALD;       // 64*68
    unsigned* Vs = Ks + 64 * ALD;       // 64*72
    unsigned* Ps = Vs + 64 * VLD;       // 64*68

    const int qb = 31 - (int)blockIdx.x;     // long CTAs first
    const int bh = blockIdx.y;
    const int bb = bh >> 4;
    const int h  = bh & 15;

    const int tid  = threadIdx.x;
    const int warp = tid >> 5;
    const int lane = tid & 31;
    const int quad = lane >> 2;              // 0..7
    const int tig  = lane & 3;               // 0..3
    const int mbase = warp * 16;

    const size_t rowbase = (size_t)bb * SEQ * QKV_COLS;
    const int qcol = h * DHEAD;

    // Load Q tile (scale folded, tf32)
    for (int idx = tid; idx < 64 * 16; idx += 128) {
        const int r  = idx >> 4;
        const int c4 = (idx & 15) * 4;
        float4 v = *(const float4*)
            &g_qkv[rowbase + (size_t)(qb * 64 + r) * QKV_COLS + qcol + c4];
        uint4 u = { f2tf32(v.x * SCALE), f2tf32(v.y * SCALE),
                    f2tf32(v.z * SCALE), f2tf32(v.w * SCALE) };
        *(uint4*)&Qs[r * ALD + c4] = u;
    }

    float o[8][4];
    #pragma unroll
    for (int nt = 0; nt < 8; nt++)
        #pragma unroll
        for (int c = 0; c < 4; c++) o[nt][c] = 0.0f;
    float m0 = -1e30f, m1 = -1e30f, l0 = 0.0f, l1 = 0.0f;

    for (int jb = 0; jb <= qb; jb++) {
        __syncthreads();   // previous iter's K/V readers done

        // Load K and V tiles (tf32)
        for (int idx = tid; idx < 64 * 16; idx += 128) {
            const int r  = idx >> 4;
            const int c4 = (idx & 15) * 4;
            const size_t rb = rowbase + (size_t)(jb * 64 + r) * QKV_COLS + qcol + c4;
            float4 kv = *(const float4*)&g_qkv[rb + INNER];
            float4 vv = *(const float4*)&g_qkv[rb + 2 * INNER];
            uint4 ku = {f2tf32(kv.x), f2tf32(kv.y), f2tf32(kv.z), f2tf32(kv.w)};
            uint4 vu = {f2tf32(vv.x), f2tf32(vv.y), f2tf32(vv.z), f2tf32(vv.w)};
            *(uint4*)&Ks[r * ALD + c4] = ku;
            *(uint4*)&Vs[r * VLD + c4] = vu;
        }
        __syncthreads();

        // S = Q @ K^T  (warp: 16 rows x 64 cols, 8 n-tiles)
        float s[8][4];
        #pragma unroll
        for (int nt = 0; nt < 8; nt++)
            #pragma unroll
            for (int c = 0; c < 4; c++) s[nt][c] = 0.0f;

        #pragma unroll
        for (int kb = 0; kb < 64; kb += 8) {
            const unsigned a0 = Qs[(mbase + quad) * ALD + kb + tig];
            const unsigned a1 = Qs[(mbase + quad + 8) * ALD + kb + tig];
            const unsigned a2 = Qs[(mbase + quad) * ALD + kb + tig + 4];
            const unsigned a3 = Qs[(mbase + quad + 8) * ALD + kb + tig + 4];
            #pragma unroll
            for (int nt = 0; nt < 8; nt++) {
                const unsigned b0 = Ks[(nt * 8 + quad) * ALD + kb + tig];
                const unsigned b1 = Ks[(nt * 8 + quad) * ALD + kb + tig + 4];
                mma_tf32(s[nt][0], s[nt][1], s[nt][2], s[nt][3],
                         a0, a1, a2, a3, b0, b1);
            }
        }

        // Causal mask on the diagonal block
        if (jb == qb) {
            const int r0 = mbase + quad, r1 = r0 + 8;
            #pragma unroll
            for (int nt = 0; nt < 8; nt++) {
                const int c0 = nt * 8 + 2 * tig, c1 = c0 + 1;
                if (c0 > r0) s[nt][0] = -1e9f;
                if (c1 > r0) s[nt][1] = -1e9f;
                if (c0 > r1) s[nt][2] = -1e9f;
                if (c1 > r1) s[nt][3] = -1e9f;
            }
        }

        // Online softmax (rows r0 = mbase+quad, r1 = r0+8)
        float mx0 = s[0][0], mx1 = s[0][2];
        #pragma unroll
        for (int nt = 0; nt < 8; nt++) {
            mx0 = fmaxf(mx0, fmaxf(s[nt][0], s[nt][1]));
            mx1 = fmaxf(mx1, fmaxf(s[nt][2], s[nt][3]));
        }
        #pragma unroll
        for (int off = 1; off <= 2; off <<= 1) {
            mx0 = fmaxf(mx0, __shfl_xor_sync(0xffffffffu, mx0, off));
            mx1 = fmaxf(mx1, __shfl_xor_sync(0xffffffffu, mx1, off));
        }
        const float mn0 = fmaxf(m0, mx0);
        const float mn1 = fmaxf(m1, mx1);
        float ps0 = 0.0f, ps1 = 0.0f;
        #pragma unroll
        for (int nt = 0; nt < 8; nt++) {
            s[nt][0] = __expf(s[nt][0] - mn0);
            s[nt][1] = __expf(s[nt][1] - mn0);
            s[nt][2] = __expf(s[nt][2] - mn1);
            s[nt][3] = __expf(s[nt][3] - mn1);
            ps0 += s[nt][0] + s[nt][1];
            ps1 += s[nt][2] + s[nt][3];
        }
        #pragma unroll
        for (int off = 1; off <= 2; off <<= 1) {
            ps0 += __shfl_xor_sync(0xffffffffu, ps0, off);
            ps1 += __shfl_xor_sync(0xffffffffu, ps1, off);
        }
        const float al0 = __expf(m0 - mn0);
        const float al1 = __expf(m1 - mn1);
        l0 = l0 * al0 + ps0;
        l1 = l1 * al1 + ps1;
        m0 = mn0;
        m1 = mn1;

        // Rescale O, stash P (tf32) in warp-private smem band
        #pragma unroll
        for (int nt = 0; nt < 8; nt++) {
            o[nt][0] *= al0; o[nt][1] *= al0;
            o[nt][2] *= al1; o[nt][3] *= al1;
            uint2 p0 = {f2tf32(s[nt][0]), f2tf32(s[nt][1])};
            uint2 p1 = {f2tf32(s[nt][2]), f2tf32(s[nt][3])};
            *(uint2*)&Ps[(mbase + quad) * ALD + nt * 8 + 2 * tig] = p0;
            *(uint2*)&Ps[(mbase + quad + 8) * ALD + nt * 8 + 2 * tig] = p1;
        }
        __syncwarp();

        // O += P @ V  (contraction over j; V as B[k=j][n=d])
        #pragma unroll
        for (int kb = 0; kb < 64; kb += 8) {
            const unsigned a0 = Ps[(mbase + quad) * ALD + kb + tig];
            const unsigned a1 = Ps[(mbase + quad + 8) * ALD + kb + tig];
            const unsigned a2 = Ps[(mbase + quad) * ALD + kb + tig + 4];
            const unsigned a3 = Ps[(mbase + quad + 8) * ALD + kb + tig + 4];
            #pragma unroll
            for (int nt = 0; nt < 8; nt++) {
                const unsigned b0 = Vs[(kb + tig) * VLD + nt * 8 + quad];
                const unsigned b1 = Vs[(kb + tig + 4) * VLD + nt * 8 + quad];
                mma_tf32(o[nt][0], o[nt][1], o[nt][2], o[nt][3],
                         a0, a1, a2, a3, b0, b1);
            }
        }
    }

    // Normalize + write
    const float i0 = 1.0f / l0;
    const float i1 = 1.0f / l1;
    const size_t nrow0 = (size_t)bb * SEQ + qb * 64 + mbase + quad;
    #pragma unroll
    for (int nt = 0; nt < 8; nt++) {
        const int c = qcol + nt * 8 + 2 * tig;
        float2 w0 = {o[nt][0] * i0, o[nt][1] * i0};
        float2 w1 = {o[nt][2] * i1, o[nt][3] * i1};
        *(float2*)&g_att[nrow0 * INNER + c] = w0;
        *(float2*)&g_att[(nrow0 + 8) * INNER + c] = w1;
    }
}

// ---------------------------------------------------------------------------
extern "C" void kernel_launch(void* const* d_in, const int* in_sizes, int n_in,
                              void* d_out, int out_size)
{
    const float* x     = (const float*)d_in[0];  // [4,2048,1024]
    const float* w_qkv = (const float*)d_in[1];  // [1024,3072]
    const float* w_out = (const float*)d_in[2];  // [1024,1024]
    const float* b_out = (const float*)d_in[3];  // [1024]
    float* out = (float*)d_out;                  // [4,2048,1024]

    float* qkv_ptr = nullptr;
    float* att_ptr = nullptr;
    cudaGetSymbolAddress((void**)&qkv_ptr, g_qkv);
    cudaGetSymbolAddress((void**)&att_ptr, g_att);

    // 1) QKV projection: [8192,1024] @ [1024,3072]  (tf32 tensor cores)
    {
        dim3 grid(QKV_COLS / 128, M_TOTAL / 128);   // (24, 64)
        tgemm128<false><<<grid, 256>>>(x, w_qkv, nullptr, qkv_ptr,
                                       M_TOTAL, QKV_COLS, DIM);
    }

    // 2) Causal flash attention (tf32 tensor cores)
    {
        const int smem_bytes = (64 * ALD * 3 + 64 * VLD) * 4;   // 70656
        cudaFuncSetAttribute(attn_mma_kernel,
                             cudaFuncAttributeMaxDynamicSharedMemorySize,
                             smem_bytes);
        dim3 grid(SEQ / 64, BATCH * HEADS);         // (32, 64)
        attn_mma_kernel<<<grid, 128, smem_bytes>>>();
    }

    // 3) Output projection with bias: [8192,1024] @ [1024,1024] + b (tf32)
    {
        dim3 grid(DIM / 128, M_TOTAL / 128);        // (8, 64)
        tgemm128<true><<<grid, 256>>>(att_ptr, w_out, b_out, out,
                                      M_TOTAL, DIM, INNER);
    }
}

// round 6
// speedup vs baseline: 2.6483x; 1.4199x over previous
#include <cuda_runtime.h>
#include <cstddef>
#include <cstdint>

#define DIM 1024
#define HEADS 16
#define DHEAD 64
#define BATCH 4
#define SEQ 2048
#define INNER 1024
#define M_TOTAL (BATCH * SEQ)          // 8192
#define QKV_COLS (3 * INNER)           // 3072
#define SCALE 0.125f                   // 64^-0.5

// Scratch (allocation-free rule: device globals)
__device__ float g_qkv[(size_t)M_TOTAL * QKV_COLS];   // [b*n, 3072] (tf32 bits)
__device__ float g_att[(size_t)M_TOTAL * INNER];      // [b*n, 1024]

// ---------------------------------------------------------------------------
// tf32 + cp.async helpers
// ---------------------------------------------------------------------------
__device__ __forceinline__ unsigned f2tf32(float f) {
    unsigned u;
    asm("cvt.rna.tf32.f32 %0, %1;" : "=r"(u) : "f"(f));
    return u;
}

__device__ __forceinline__ void mma_tf32(float& d0, float& d1, float& d2, float& d3,
                                         unsigned a0, unsigned a1, unsigned a2, unsigned a3,
                                         unsigned b0, unsigned b1)
{
    asm volatile(
        "mma.sync.aligned.m16n8k8.row.col.f32.tf32.tf32.f32 "
        "{%0,%1,%2,%3}, {%4,%5,%6,%7}, {%8,%9}, {%0,%1,%2,%3};"
        : "+f"(d0), "+f"(d1), "+f"(d2), "+f"(d3)
        : "r"(a0), "r"(a1), "r"(a2), "r"(a3), "r"(b0), "r"(b1));
}

__device__ __forceinline__ void cp16(void* dst_smem, const void* src_gmem) {
    unsigned s = (unsigned)__cvta_generic_to_shared(dst_smem);
    asm volatile("cp.async.cg.shared.global [%0], [%1], 16;"
                 :: "r"(s), "l"(src_gmem));
}
#define CP_COMMIT() asm volatile("cp.async.commit_group;")
#define CP_WAIT0()  asm volatile("cp.async.wait_group 0;")

// ---------------------------------------------------------------------------
// tf32 tensor-core GEMM. CVT: epilogue stores tf32-rounded values so the
// consumer (attention) can skip conversion and use raw cp.async.
// ---------------------------------------------------------------------------
#define LDPAD 136

template <bool BIAS, bool CVT>
__global__ __launch_bounds__(256)
void tgemm128(const float* __restrict__ A, const float* __restrict__ Bw,
              const float* __restrict__ bias, float* __restrict__ C,
              int M, int Nc, int K)
{
    __shared__ unsigned As[2][16][LDPAD];
    __shared__ unsigned Bs[2][16][LDPAD];

    const int bx = blockIdx.x;
    const int by = blockIdx.y;
    const int tid = threadIdx.x;
    const int warp = tid >> 5;
    const int lane = tid & 31;
    const int quad = lane >> 2;
    const int tig  = lane & 3;
    const int warp_m = warp >> 2;
    const int warp_n = warp & 3;

    const int rowA = by * 128;
    const int colB = bx * 128;

    const int aRow0  = tid >> 2;
    const int aChunk = (tid & 3) * 4;
    const int bK0 = tid >> 5;
    const int bN4 = (lane) * 4;

    float acc[4][4][4];
    #pragma unroll
    for (int mt = 0; mt < 4; mt++)
        #pragma unroll
        for (int nt = 0; nt < 4; nt++)
            #pragma unroll
            for (int r = 0; r < 4; r++) acc[mt][nt][r] = 0.0f;

    {
        float4 a0 = *(const float4*)&A[(size_t)(rowA + aRow0) * K + aChunk];
        float4 a1 = *(const float4*)&A[(size_t)(rowA + aRow0 + 64) * K + aChunk];
        As[0][aChunk + 0][aRow0] = f2tf32(a0.x);
        As[0][aChunk + 1][aRow0] = f2tf32(a0.y);
        As[0][aChunk + 2][aRow0] = f2tf32(a0.z);
        As[0][aChunk + 3][aRow0] = f2tf32(a0.w);
        As[0][aChunk + 0][aRow0 + 64] = f2tf32(a1.x);
        As[0][aChunk + 1][aRow0 + 64] = f2tf32(a1.y);
        As[0][aChunk + 2][aRow0 + 64] = f2tf32(a1.z);
        As[0][aChunk + 3][aRow0 + 64] = f2tf32(a1.w);

        float4 b0 = *(const float4*)&Bw[(size_t)bK0 * Nc + colB + bN4];
        float4 b1 = *(const float4*)&Bw[(size_t)(bK0 + 8) * Nc + colB + bN4];
        uint4 u0 = {f2tf32(b0.x), f2tf32(b0.y), f2tf32(b0.z), f2tf32(b0.w)};
        uint4 u1 = {f2tf32(b1.x), f2tf32(b1.y), f2tf32(b1.z), f2tf32(b1.w)};
        *(uint4*)&Bs[0][bK0][bN4] = u0;
        *(uint4*)&Bs[0][bK0 + 8][bN4] = u1;
    }
    __syncthreads();

    int buf = 0;
    for (int k0 = 0; k0 < K; k0 += 16) {
        float4 pa0, pa1, pb0, pb1;
        const bool more = (k0 + 16 < K);
        if (more) {
            pa0 = *(const float4*)&A[(size_t)(rowA + aRow0) * K + k0 + 16 + aChunk];
            pa1 = *(const float4*)&A[(size_t)(rowA + aRow0 + 64) * K + k0 + 16 + aChunk];
            pb0 = *(const float4*)&Bw[(size_t)(k0 + 16 + bK0) * Nc + colB + bN4];
            pb1 = *(const float4*)&Bw[(size_t)(k0 + 16 + bK0 + 8) * Nc + colB + bN4];
        }

        #pragma unroll
        for (int ks = 0; ks < 2; ks++) {
            const int kb = ks * 8;
            unsigned af[4][4];
            #pragma unroll
            for (int mt = 0; mt < 4; mt++) {
                const int rb = warp_m * 64 + mt * 16 + quad;
                af[mt][0] = As[buf][kb + tig][rb];
                af[mt][1] = As[buf][kb + tig][rb + 8];
                af[mt][2] = As[buf][kb + tig + 4][rb];
                af[mt][3] = As[buf][kb + tig + 4][rb + 8];
            }
            unsigned bf[4][2];
            #pragma unroll
            for (int nt = 0; nt < 4; nt++) {
                const int nb = warp_n * 32 + nt * 8 + quad;
                bf[nt][0] = Bs[buf][kb + tig][nb];
                bf[nt][1] = Bs[buf][kb + tig + 4][nb];
            }
            #pragma unroll
            for (int mt = 0; mt < 4; mt++)
                #pragma unroll
                for (int nt = 0; nt < 4; nt++)
                    mma_tf32(acc[mt][nt][0], acc[mt][nt][1],
                             acc[mt][nt][2], acc[mt][nt][3],
                             af[mt][0], af[mt][1], af[mt][2], af[mt][3],
                             bf[nt][0], bf[nt][1]);
        }

        if (more) {
            const int nb = buf ^ 1;
            As[nb][aChunk + 0][aRow0] = f2tf32(pa0.x);
            As[nb][aChunk + 1][aRow0] = f2tf32(pa0.y);
            As[nb][aChunk + 2][aRow0] = f2tf32(pa0.z);
            As[nb][aChunk + 3][aRow0] = f2tf32(pa0.w);
            As[nb][aChunk + 0][aRow0 + 64] = f2tf32(pa1.x);
            As[nb][aChunk + 1][aRow0 + 64] = f2tf32(pa1.y);
            As[nb][aChunk + 2][aRow0 + 64] = f2tf32(pa1.z);
            As[nb][aChunk + 3][aRow0 + 64] = f2tf32(pa1.w);
            uint4 u0 = {f2tf32(pb0.x), f2tf32(pb0.y), f2tf32(pb0.z), f2tf32(pb0.w)};
            uint4 u1 = {f2tf32(pb1.x), f2tf32(pb1.y), f2tf32(pb1.z), f2tf32(pb1.w)};
            *(uint4*)&Bs[nb][bK0][bN4] = u0;
            *(uint4*)&Bs[nb][bK0 + 8][bN4] = u1;
        }
        __syncthreads();
        buf ^= 1;
    }

    #pragma unroll
    for (int mt = 0; mt < 4; mt++) {
        const int r0 = rowA + warp_m * 64 + mt * 16 + quad;
        #pragma unroll
        for (int nt = 0; nt < 4; nt++) {
            const int c = colB + warp_n * 32 + nt * 8 + 2 * tig;
            float bx0 = 0.f, bx1 = 0.f;
            if (BIAS) { bx0 = bias[c]; bx1 = bias[c + 1]; }
            float2 v0 = {acc[mt][nt][0] + bx0, acc[mt][nt][1] + bx1};
            float2 v1 = {acc[mt][nt][2] + bx0, acc[mt][nt][3] + bx1};
            if (CVT) {
                v0.x = __uint_as_float(f2tf32(v0.x));
                v0.y = __uint_as_float(f2tf32(v0.y));
                v1.x = __uint_as_float(f2tf32(v1.x));
                v1.y = __uint_as_float(f2tf32(v1.y));
            }
            *(float2*)&C[(size_t)r0 * Nc + c] = v0;
            *(float2*)&C[(size_t)(r0 + 8) * Nc + c] = v1;
        }
    }
}

// ---------------------------------------------------------------------------
// Tensor-core causal flash attention, cp.async double-buffered K/V.
// CTA = (b, h, 128-row Q block), 8 warps; warp owns 16 rows x 64 cols.
// g_qkv is already tf32-rounded (GEMM epilogue), so loads are raw cp.async.
// SCALE applied to S in fp32 post-mma (exact, power of two).
// Strides: Q/K/P rows = 68 words, V rows = 72 words (conflict-free gathers).
// ---------------------------------------------------------------------------
#define ALD 68
#define VLD 72

__global__ __launch_bounds__(256)
void attn_mma_kernel()
{
    extern __shared__ unsigned smu[];
    unsigned* Qs = smu;                  // 128*68
    unsigned* Ps = Qs + 128 * ALD;       // 128*68
    unsigned* Kb[2];
    unsigned* Vb[2];
    Kb[0] = Ps + 128 * ALD;
    Vb[0] = Kb[0] + 64 * ALD;
    Kb[1] = Vb[0] + 64 * VLD;
    Vb[1] = Kb[1] + 64 * ALD;

    const int qb = 15 - (int)blockIdx.x;     // long CTAs first; 128-row block
    const int bh = blockIdx.y;
    const int bb = bh >> 4;
    const int h  = bh & 15;

    const int tid  = threadIdx.x;
    const int warp = tid >> 5;               // 0..7
    const int lane = tid & 31;
    const int quad = lane >> 2;              // 0..7
    const int tig  = lane & 3;               // 0..3
    const int mbase = warp * 16;

    const size_t rowbase = (size_t)bb * SEQ * QKV_COLS;
    const int qcol = h * DHEAD;

    // Async-load Q tile (128 rows x 64)
    #pragma unroll
    for (int i = 0; i < 8; i++) {
        const int idx = tid + i * 256;       // 0..2047
        const int r  = idx >> 4;
        const int c4 = (idx & 15) * 4;
        cp16(&Qs[r * ALD + c4],
             &g_qkv[rowbase + (size_t)(qb * 128 + r) * QKV_COLS + qcol + c4]);
    }
    // Async-load K/V tile jb=0 into buffer 0
    {
        #pragma unroll
        for (int i = 0; i < 8; i++) {
            const int idx = tid + i * 256;   // 0..2047
            const int half = idx >> 10;      // 0:K 1:V
            const int r  = (idx & 1023) >> 4;
            const int c4 = (idx & 15) * 4;
            const float* g = &g_qkv[rowbase + (size_t)r * QKV_COLS +
                                    (half ? 2 * INNER : INNER) + qcol + c4];
            if (half) cp16(&Vb[0][r * VLD + c4], g);
            else      cp16(&Kb[0][r * ALD + c4], g);
        }
    }
    CP_COMMIT();
    CP_WAIT0();
    __syncthreads();

    float o[8][4];
    #pragma unroll
    for (int nt = 0; nt < 8; nt++)
        #pragma unroll
        for (int c = 0; c < 4; c++) o[nt][c] = 0.0f;
    float m0 = -1e30f, m1 = -1e30f, l0 = 0.0f, l1 = 0.0f;

    const int jmax = 2 * qb + 1;             // last 64-col K block index

    int buf = 0;
    for (int jb = 0; jb <= jmax; jb++) {
        // Kick off next tile's loads (overlaps with this tile's compute)
        if (jb < jmax) {
            unsigned* Kn = Kb[buf ^ 1];
            unsigned* Vn = Vb[buf ^ 1];
            #pragma unroll
            for (int i = 0; i < 8; i++) {
                const int idx = tid + i * 256;
                const int half = idx >> 10;
                const int r  = (idx & 1023) >> 4;
                const int c4 = (idx & 15) * 4;
                const float* g = &g_qkv[rowbase +
                                        (size_t)((jb + 1) * 64 + r) * QKV_COLS +
                                        (half ? 2 * INNER : INNER) + qcol + c4];
                if (half) cp16(&Vn[r * VLD + c4], g);
                else      cp16(&Kn[r * ALD + c4], g);
            }
            CP_COMMIT();
        }

        unsigned* Kc = Kb[buf];
        unsigned* Vc = Vb[buf];

        // S = Q @ K^T  (warp: 16 rows x 64 cols)
        float s[8][4];
        #pragma unroll
        for (int nt = 0; nt < 8; nt++)
            #pragma unroll
            for (int c = 0; c < 4; c++) s[nt][c] = 0.0f;

        #pragma unroll
        for (int kb = 0; kb < 64; kb += 8) {
            const unsigned a0 = Qs[(mbase + quad) * ALD + kb + tig];
            const unsigned a1 = Qs[(mbase + quad + 8) * ALD + kb + tig];
            const unsigned a2 = Qs[(mbase + quad) * ALD + kb + tig + 4];
            const unsigned a3 = Qs[(mbase + quad + 8) * ALD + kb + tig + 4];
            #pragma unroll
            for (int nt = 0; nt < 8; nt++) {
                const unsigned b0 = Kc[(nt * 8 + quad) * ALD + kb + tig];
                const unsigned b1 = Kc[(nt * 8 + quad) * ALD + kb + tig + 4];
                mma_tf32(s[nt][0], s[nt][1], s[nt][2], s[nt][3],
                         a0, a1, a2, a3, b0, b1);
            }
        }

        // Scale (exact) + causal mask on the last two K blocks
        #pragma unroll
        for (int nt = 0; nt < 8; nt++)
            #pragma unroll
            for (int c = 0; c < 4; c++) s[nt][c] *= SCALE;

        if (jb >= 2 * qb) {
            const int r0 = mbase + quad, r1 = r0 + 8;   // local rows in [0,128)
            const int coff = (jb - 2 * qb) * 64;
            #pragma unroll
            for (int nt = 0; nt < 8; nt++) {
                const int c0 = coff + nt * 8 + 2 * tig, c1 = c0 + 1;
                if (c0 > r0) s[nt][0] = -1e9f;
                if (c1 > r0) s[nt][1] = -1e9f;
                if (c0 > r1) s[nt][2] = -1e9f;
                if (c1 > r1) s[nt][3] = -1e9f;
            }
        }

        // Online softmax (rows r0 = mbase+quad, r1 = r0+8; quad groups)
        float mx0 = s[0][0], mx1 = s[0][2];
        #pragma unroll
        for (int nt = 0; nt < 8; nt++) {
            mx0 = fmaxf(mx0, fmaxf(s[nt][0], s[nt][1]));
            mx1 = fmaxf(mx1, fmaxf(s[nt][2], s[nt][3]));
        }
        #pragma unroll
        for (int off = 1; off <= 2; off <<= 1) {
            mx0 = fmaxf(mx0, __shfl_xor_sync(0xffffffffu, mx0, off));
            mx1 = fmaxf(mx1, __shfl_xor_sync(0xffffffffu, mx1, off));
        }
        const float mn0 = fmaxf(m0, mx0);
        const float mn1 = fmaxf(m1, mx1);
        float ps0 = 0.0f, ps1 = 0.0f;
        #pragma unroll
        for (int nt = 0; nt < 8; nt++) {
            s[nt][0] = __expf(s[nt][0] - mn0);
            s[nt][1] = __expf(s[nt][1] - mn0);
            s[nt][2] = __expf(s[nt][2] - mn1);
            s[nt][3] = __expf(s[nt][3] - mn1);
            ps0 += s[nt][0] + s[nt][1];
            ps1 += s[nt][2] + s[nt][3];
        }
        #pragma unroll
        for (int off = 1; off <= 2; off <<= 1) {
            ps0 += __shfl_xor_sync(0xffffffffu, ps0, off);
            ps1 += __shfl_xor_sync(0xffffffffu, ps1, off);
        }
        const float al0 = __expf(m0 - mn0);
        const float al1 = __expf(m1 - mn1);
        l0 = l0 * al0 + ps0;
        l1 = l1 * al1 + ps1;
        m0 = mn0;
        m1 = mn1;

        // Rescale O, stash P (tf32) in warp-private smem band
        #pragma unroll
        for (int nt = 0; nt < 8; nt++) {
            o[nt][0] *= al0; o[nt][1] *= al0;
            o[nt][2] *= al1; o[nt][3] *= al1;
            uint2 p0 = {f2tf32(s[nt][0]), f2tf32(s[nt][1])};
            uint2 p1 = {f2tf32(s[nt][2]), f2tf32(s[nt][3])};
            *(uint2*)&Ps[(mbase + quad) * ALD + nt * 8 + 2 * tig] = p0;
            *(uint2*)&Ps[(mbase + quad + 8) * ALD + nt * 8 + 2 * tig] = p1;
        }
        __syncwarp();

        // O += P @ V
        #pragma unroll
        for (int kb = 0; kb < 64; kb += 8) {
            const unsigned a0 = Ps[(mbase + quad) * ALD + kb + tig];
            const unsigned a1 = Ps[(mbase + quad + 8) * ALD + kb + tig];
            const unsigned a2 = Ps[(mbase + quad) * ALD + kb + tig + 4];
            const unsigned a3 = Ps[(mbase + quad + 8) * ALD + kb + tig + 4];
            #pragma unroll
            for (int nt = 0; nt < 8; nt++) {
                const unsigned b0 = Vc[(kb + tig) * VLD + nt * 8 + quad];
                const unsigned b1 = Vc[(kb + tig + 4) * VLD + nt * 8 + quad];
                mma_tf32(o[nt][0], o[nt][1], o[nt][2], o[nt][3],
                         a0, a1, a2, a3, b0, b1);
            }
        }

        // Next tile must have landed; barrier also protects buffer reuse
        if (jb < jmax) CP_WAIT0();
        __syncthreads();
        buf ^= 1;
    }

    // Normalize + write
    const float i0 = 1.0f / l0;
    const float i1 = 1.0f / l1;
    const size_t nrow0 = (size_t)bb * SEQ + qb * 128 + mbase + quad;
    #pragma unroll
    for (int nt = 0; nt < 8; nt++) {
        const int c = qcol + nt * 8 + 2 * tig;
        float2 w0 = {o[nt][0] * i0, o[nt][1] * i0};
        float2 w1 = {o[nt][2] * i1, o[nt][3] * i1};
        *(float2*)&g_att[nrow0 * INNER + c] = w0;
        *(float2*)&g_att[(nrow0 + 8) * INNER + c] = w1;
    }
}

// ---------------------------------------------------------------------------
extern "C" void kernel_launch(void* const* d_in, const int* in_sizes, int n_in,
                              void* d_out, int out_size)
{
    const float* x     = (const float*)d_in[0];  // [4,2048,1024]
    const float* w_qkv = (const float*)d_in[1];  // [1024,3072]
    const float* w_out = (const float*)d_in[2];  // [1024,1024]
    const float* b_out = (const float*)d_in[3];  // [1024]
    float* out = (float*)d_out;                  // [4,2048,1024]

    float* qkv_ptr = nullptr;
    float* att_ptr = nullptr;
    cudaGetSymbolAddress((void**)&qkv_ptr, g_qkv);
    cudaGetSymbolAddress((void**)&att_ptr, g_att);

    // 1) QKV projection (tf32 mma); epilogue rounds output to tf32
    {
        dim3 grid(QKV_COLS / 128, M_TOTAL / 128);   // (24, 64)
        tgemm128<false, true><<<grid, 256>>>(x, w_qkv, nullptr, qkv_ptr,
                                             M_TOTAL, QKV_COLS, DIM);
    }

    // 2) Causal flash attention (tf32 mma, cp.async double-buffered K/V)
    {
        const int smem_words = 128 * ALD * 2 + 2 * (64 * ALD + 64 * VLD);
        const int smem_bytes = smem_words * 4;      // 141312
        cudaFuncSetAttribute(attn_mma_kernel,
                             cudaFuncAttributeMaxDynamicSharedMemorySize,
                             smem_bytes);
        dim3 grid(SEQ / 128, BATCH * HEADS);        // (16, 64)
        attn_mma_kernel<<<grid, 256, smem_bytes>>>();
    }

    // 3) Output projection with bias (tf32 mma, fp32 output)
    {
        dim3 grid(DIM / 128, M_TOTAL / 128);        // (8, 64)
        tgemm128<true, false><<<grid, 256>>>(att_ptr, w_out, b_out, out,
                                             M_TOTAL, DIM, INNER);
    }
}

// round 16
// speedup vs baseline: 3.0510x; 1.1520x over previous
#include <cuda_runtime.h>
#include <cstddef>
#include <cstdint>

#define DIM 1024
#define HEADS 16
#define DHEAD 64
#define BATCH 4
#define SEQ 2048
#define INNER 1024
#define M_TOTAL (BATCH * SEQ)          // 8192
#define QKV_COLS (3 * INNER)           // 3072
#define SCALE 0.125f                   // 64^-0.5

// Scratch (allocation-free rule: device globals)
__device__ float g_qkv[(size_t)M_TOTAL * QKV_COLS];   // [b*n, 3072] (tf32 bits)
__device__ float g_att[(size_t)M_TOTAL * INNER];      // [b*n, 1024]

// ---------------------------------------------------------------------------
// tf32 + cp.async + ldmatrix helpers
// ---------------------------------------------------------------------------
__device__ __forceinline__ unsigned f2tf32(float f) {
    unsigned u;
    asm("cvt.rna.tf32.f32 %0, %1;" : "=r"(u) : "f"(f));
    return u;
}

__device__ __forceinline__ void mma_tf32(float& d0, float& d1, float& d2, float& d3,
                                         unsigned a0, unsigned a1, unsigned a2, unsigned a3,
                                         unsigned b0, unsigned b1)
{
    asm volatile(
        "mma.sync.aligned.m16n8k8.row.col.f32.tf32.tf32.f32 "
        "{%0,%1,%2,%3}, {%4,%5,%6,%7}, {%8,%9}, {%0,%1,%2,%3};"
        : "+f"(d0), "+f"(d1), "+f"(d2), "+f"(d3)
        : "r"(a0), "r"(a1), "r"(a2), "r"(a3), "r"(b0), "r"(b1));
}

// ldmatrix x4: b32 view — thread gets element (lane>>2, lane&3) of each 8x4
// b32 tile; lanes 0-7/8-15/16-23/24-31 provide row addresses of tiles 0..3.
__device__ __forceinline__ void ldsm_x4(unsigned& r0, unsigned& r1,
                                        unsigned& r2, unsigned& r3,
                                        const void* p)
{
    unsigned a = (unsigned)__cvta_generic_to_shared(p);
    asm volatile("ldmatrix.sync.aligned.m8n8.x4.shared.b16 {%0,%1,%2,%3}, [%4];"
                 : "=r"(r0), "=r"(r1), "=r"(r2), "=r"(r3) : "r"(a));
}

__device__ __forceinline__ void cp16(void* dst_smem, const void* src_gmem) {
    unsigned s = (unsigned)__cvta_generic_to_shared(dst_smem);
    asm volatile("cp.async.cg.shared.global [%0], [%1], 16;"
                 :: "r"(s), "l"(src_gmem));
}
#define CP_COMMIT() asm volatile("cp.async.commit_group;")
#define CP_WAIT0()  asm volatile("cp.async.wait_group 0;")

// ---------------------------------------------------------------------------
// tf32 tensor-core GEMM. A fragments via ldmatrix (As m-major, stride 20:
// 20m mod 32 tiles all banks -> conflict-free LDSM). B fragments scalar LDS
// (K-major, LDPAD=136, conflict-free). CVT: epilogue rounds output to tf32.
// ---------------------------------------------------------------------------
#define LDPAD 136
#define SA 20

template <bool BIAS, bool CVT>
__global__ __launch_bounds__(256)
void tgemm128(const float* __restrict__ A, const float* __restrict__ Bw,
              const float* __restrict__ bias, float* __restrict__ C,
              int M, int Nc, int K)
{
    __shared__ unsigned As[2][128][SA];     // m-major
    __shared__ unsigned Bs[2][16][LDPAD];   // k-major

    const int bx = blockIdx.x;
    const int by = blockIdx.y;
    const int tid = threadIdx.x;
    const int warp = tid >> 5;
    const int lane = tid & 31;
    const int quad = lane >> 2;
    const int tig  = lane & 3;
    const int warp_m = warp >> 2;
    const int warp_n = warp & 3;

    // ldmatrix per-lane address components
    const int g  = lane >> 3;               // tile index 0..3
    const int lr = lane & 7;                // row within tile
    const int arow = (g & 1) * 8 + lr;      // +0/+8 row block
    const int acol = (g >> 1) * 4;          // +0/+4 k block

    const int rowA = by * 128;
    const int colB = bx * 128;

    const int aRow0  = tid >> 2;            // 0..63 (second +64)
    const int aChunk = (tid & 3) * 4;       // k offset 0,4,8,12
    const int bK0 = tid >> 5;
    const int bN4 = lane * 4;

    float acc[4][4][4];
    #pragma unroll
    for (int mt = 0; mt < 4; mt++)
        #pragma unroll
        for (int nt = 0; nt < 4; nt++)
            #pragma unroll
            for (int r = 0; r < 4; r++) acc[mt][nt][r] = 0.0f;

    {
        float4 a0 = *(const float4*)&A[(size_t)(rowA + aRow0) * K + aChunk];
        float4 a1 = *(const float4*)&A[(size_t)(rowA + aRow0 + 64) * K + aChunk];
        uint4 u0 = {f2tf32(a0.x), f2tf32(a0.y), f2tf32(a0.z), f2tf32(a0.w)};
        uint4 u1 = {f2tf32(a1.x), f2tf32(a1.y), f2tf32(a1.z), f2tf32(a1.w)};
        *(uint4*)&As[0][aRow0][aChunk] = u0;
        *(uint4*)&As[0][aRow0 + 64][aChunk] = u1;

        float4 b0 = *(const float4*)&Bw[(size_t)bK0 * Nc + colB + bN4];
        float4 b1 = *(const float4*)&Bw[(size_t)(bK0 + 8) * Nc + colB + bN4];
        uint4 v0 = {f2tf32(b0.x), f2tf32(b0.y), f2tf32(b0.z), f2tf32(b0.w)};
        uint4 v1 = {f2tf32(b1.x), f2tf32(b1.y), f2tf32(b1.z), f2tf32(b1.w)};
        *(uint4*)&Bs[0][bK0][bN4] = v0;
        *(uint4*)&Bs[0][bK0 + 8][bN4] = v1;
    }
    __syncthreads();

    int buf = 0;
    for (int k0 = 0; k0 < K; k0 += 16) {
        float4 pa0, pa1, pb0, pb1;
        const bool more = (k0 + 16 < K);
        if (more) {
            pa0 = *(const float4*)&A[(size_t)(rowA + aRow0) * K + k0 + 16 + aChunk];
            pa1 = *(const float4*)&A[(size_t)(rowA + aRow0 + 64) * K + k0 + 16 + aChunk];
            pb0 = *(const float4*)&Bw[(size_t)(k0 + 16 + bK0) * Nc + colB + bN4];
            pb1 = *(const float4*)&Bw[(size_t)(k0 + 16 + bK0 + 8) * Nc + colB + bN4];
        }

        #pragma unroll
        for (int ks = 0; ks < 2; ks++) {
            const int kb = ks * 8;
            unsigned af[4][4];
            #pragma unroll
            for (int mt = 0; mt < 4; mt++)
                ldsm_x4(af[mt][0], af[mt][1], af[mt][2], af[mt][3],
                        &As[buf][warp_m * 64 + mt * 16 + arow][kb + acol]);
            unsigned bf[4][2];
            #pragma unroll
            for (int nt = 0; nt < 4; nt++) {
                const int nb = warp_n * 32 + nt * 8 + quad;
                bf[nt][0] = Bs[buf][kb + tig][nb];
                bf[nt][1] = Bs[buf][kb + tig + 4][nb];
            }
            #pragma unroll
            for (int mt = 0; mt < 4; mt++)
                #pragma unroll
                for (int nt = 0; nt < 4; nt++)
                    mma_tf32(acc[mt][nt][0], acc[mt][nt][1],
                             acc[mt][nt][2], acc[mt][nt][3],
                             af[mt][0], af[mt][1], af[mt][2], af[mt][3],
                             bf[nt][0], bf[nt][1]);
        }

        if (more) {
            const int nb = buf ^ 1;
            uint4 u0 = {f2tf32(pa0.x), f2tf32(pa0.y), f2tf32(pa0.z), f2tf32(pa0.w)};
            uint4 u1 = {f2tf32(pa1.x), f2tf32(pa1.y), f2tf32(pa1.z), f2tf32(pa1.w)};
            *(uint4*)&As[nb][aRow0][aChunk] = u0;
            *(uint4*)&As[nb][aRow0 + 64][aChunk] = u1;
            uint4 v0 = {f2tf32(pb0.x), f2tf32(pb0.y), f2tf32(pb0.z), f2tf32(pb0.w)};
            uint4 v1 = {f2tf32(pb1.x), f2tf32(pb1.y), f2tf32(pb1.z), f2tf32(pb1.w)};
            *(uint4*)&Bs[nb][bK0][bN4] = v0;
            *(uint4*)&Bs[nb][bK0 + 8][bN4] = v1;
        }
        __syncthreads();
        buf ^= 1;
    }

    #pragma unroll
    for (int mt = 0; mt < 4; mt++) {
        const int r0 = rowA + warp_m * 64 + mt * 16 + quad;
        #pragma unroll
        for (int nt = 0; nt < 4; nt++) {
            const int c = colB + warp_n * 32 + nt * 8 + 2 * tig;
            float bx0 = 0.f, bx1 = 0.f;
            if (BIAS) { bx0 = bias[c]; bx1 = bias[c + 1]; }
            float2 v0 = {acc[mt][nt][0] + bx0, acc[mt][nt][1] + bx1};
            float2 v1 = {acc[mt][nt][2] + bx0, acc[mt][nt][3] + bx1};
            if (CVT) {
                v0.x = __uint_as_float(f2tf32(v0.x));
                v0.y = __uint_as_float(f2tf32(v0.y));
                v1.x = __uint_as_float(f2tf32(v1.x));
                v1.y = __uint_as_float(f2tf32(v1.y));
            }
            *(float2*)&C[(size_t)r0 * Nc + c] = v0;
            *(float2*)&C[(size_t)(r0 + 8) * Nc + c] = v1;
        }
    }
}

// ---------------------------------------------------------------------------
// Tensor-core causal flash attention, cp.async double-buffered K/V.
// Q/K/P fragment loads via ldmatrix (ALD=68: 68r mod 32 = 4r -> conflict-
// free LDSM with the existing layout). V stays scalar LDS (k-major).
// ---------------------------------------------------------------------------
#define ALD 68
#define VLD 72

__global__ __launch_bounds__(256)
void attn_mma_kernel()
{
    extern __shared__ unsigned smu[];
    unsigned* Qs = smu;                  // 128*68
    unsigned* Ps = Qs + 128 * ALD;       // 128*68
    unsigned* Kb[2];
    unsigned* Vb[2];
    Kb[0] = Ps + 128 * ALD;
    Vb[0] = Kb[0] + 64 * ALD;
    Kb[1] = Vb[0] + 64 * VLD;
    Vb[1] = Kb[1] + 64 * ALD;

    const int qb = 15 - (int)blockIdx.x;     // long CTAs first; 128-row block
    const int bh = blockIdx.y;
    const int bb = bh >> 4;
    const int h  = bh & 15;

    const int tid  = threadIdx.x;
    const int warp = tid >> 5;               // 0..7
    const int lane = tid & 31;
    const int quad = lane >> 2;              // 0..7
    const int tig  = lane & 3;               // 0..3
    const int mbase = warp * 16;

    // ldmatrix per-lane address components
    const int g  = lane >> 3;
    const int lr = lane & 7;
    const int arow = (g & 1) * 8 + lr;       // A tiles: +0/+8 rows, +0/+4 k
    const int acol = (g >> 1) * 4;
    const int brow = (g >> 1) * 8 + lr;      // B tiles: +0/+8 n, +0/+4 k
    const int bcol = (g & 1) * 4;

    const size_t rowbase = (size_t)bb * SEQ * QKV_COLS;
    const int qcol = h * DHEAD;

    // Async-load Q tile (128 rows x 64)
    #pragma unroll
    for (int i = 0; i < 8; i++) {
        const int idx = tid + i * 256;
        const int r  = idx >> 4;
        const int c4 = (idx & 15) * 4;
        cp16(&Qs[r * ALD + c4],
             &g_qkv[rowbase + (size_t)(qb * 128 + r) * QKV_COLS + qcol + c4]);
    }
    // Async-load K/V tile jb=0 into buffer 0
    {
        #pragma unroll
        for (int i = 0; i < 8; i++) {
            const int idx = tid + i * 256;
            const int half = idx >> 10;
            const int r  = (idx & 1023) >> 4;
            const int c4 = (idx & 15) * 4;
            const float* gm = &g_qkv[rowbase + (size_t)r * QKV_COLS +
                                     (half ? 2 * INNER : INNER) + qcol + c4];
            if (half) cp16(&Vb[0][r * VLD + c4], gm);
            else      cp16(&Kb[0][r * ALD + c4], gm);
        }
    }
    CP_COMMIT();
    CP_WAIT0();
    __syncthreads();

    float o[8][4];
    #pragma unroll
    for (int nt = 0; nt < 8; nt++)
        #pragma unroll
        for (int c = 0; c < 4; c++) o[nt][c] = 0.0f;
    float m0 = -1e30f, m1 = -1e30f, l0 = 0.0f, l1 = 0.0f;

    const int jmax = 2 * qb + 1;

    int buf = 0;
    for (int jb = 0; jb <= jmax; jb++) {
        if (jb < jmax) {
            unsigned* Kn = Kb[buf ^ 1];
            unsigned* Vn = Vb[buf ^ 1];
            #pragma unroll
            for (int i = 0; i < 8; i++) {
                const int idx = tid + i * 256;
                const int half = idx >> 10;
                const int r  = (idx & 1023) >> 4;
                const int c4 = (idx & 15) * 4;
                const float* gm = &g_qkv[rowbase +
                                         (size_t)((jb + 1) * 64 + r) * QKV_COLS +
                                         (half ? 2 * INNER : INNER) + qcol + c4];
                if (half) cp16(&Vn[r * VLD + c4], gm);
                else      cp16(&Kn[r * ALD + c4], gm);
            }
            CP_COMMIT();
        }

        unsigned* Kc = Kb[buf];
        unsigned* Vc = Vb[buf];

        // S = Q @ K^T  via LDSM fragments
        float s[8][4];
        #pragma unroll
        for (int nt = 0; nt < 8; nt++)
            #pragma unroll
            for (int c = 0; c < 4; c++) s[nt][c] = 0.0f;

        #pragma unroll
        for (int kb = 0; kb < 64; kb += 8) {
            unsigned a0, a1, a2, a3;
            ldsm_x4(a0, a1, a2, a3, &Qs[(mbase + arow) * ALD + kb + acol]);
            #pragma unroll
            for (int np = 0; np < 4; np++) {
                unsigned b00, b01, b10, b11;
                ldsm_x4(b00, b01, b10, b11,
                        &Kc[(np * 16 + brow) * ALD + kb + bcol]);
                mma_tf32(s[2 * np][0], s[2 * np][1], s[2 * np][2], s[2 * np][3],
                         a0, a1, a2, a3, b00, b01);
                mma_tf32(s[2 * np + 1][0], s[2 * np + 1][1],
                         s[2 * np + 1][2], s[2 * np + 1][3],
                         a0, a1, a2, a3, b10, b11);
            }
        }

        // Scale (exact) + causal mask on the last two K blocks
        #pragma unroll
        for (int nt = 0; nt < 8; nt++)
            #pragma unroll
            for (int c = 0; c < 4; c++) s[nt][c] *= SCALE;

        if (jb >= 2 * qb) {
            const int r0 = mbase + quad, r1 = r0 + 8;
            const int coff = (jb - 2 * qb) * 64;
            #pragma unroll
            for (int nt = 0; nt < 8; nt++) {
                const int c0 = coff + nt * 8 + 2 * tig, c1 = c0 + 1;
                if (c0 > r0) s[nt][0] = -1e9f;
                if (c1 > r0) s[nt][1] = -1e9f;
                if (c0 > r1) s[nt][2] = -1e9f;
                if (c1 > r1) s[nt][3] = -1e9f;
            }
        }

        // Online softmax (rows r0 = mbase+quad, r1 = r0+8; quad groups)
        float mx0 = s[0][0], mx1 = s[0][2];
        #pragma unroll
        for (int nt = 0; nt < 8; nt++) {
            mx0 = fmaxf(mx0, fmaxf(s[nt][0], s[nt][1]));
            mx1 = fmaxf(mx1, fmaxf(s[nt][2], s[nt][3]));
        }
        #pragma unroll
        for (int off = 1; off <= 2; off <<= 1) {
            mx0 = fmaxf(mx0, __shfl_xor_sync(0xffffffffu, mx0, off));
            mx1 = fmaxf(mx1, __shfl_xor_sync(0xffffffffu, mx1, off));
        }
        const float mn0 = fmaxf(m0, mx0);
        const float mn1 = fmaxf(m1, mx1);
        float ps0 = 0.0f, ps1 = 0.0f;
        #pragma unroll
        for (int nt = 0; nt < 8; nt++) {
            s[nt][0] = __expf(s[nt][0] - mn0);
            s[nt][1] = __expf(s[nt][1] - mn0);
            s[nt][2] = __expf(s[nt][2] - mn1);
            s[nt][3] = __expf(s[nt][3] - mn1);
            ps0 += s[nt][0] + s[nt][1];
            ps1 += s[nt][2] + s[nt][3];
        }
        #pragma unroll
        for (int off = 1; off <= 2; off <<= 1) {
            ps0 += __shfl_xor_sync(0xffffffffu, ps0, off);
            ps1 += __shfl_xor_sync(0xffffffffu, ps1, off);
        }
        const float al0 = __expf(m0 - mn0);
        const float al1 = __expf(m1 - mn1);
        l0 = l0 * al0 + ps0;
        l1 = l1 * al1 + ps1;
        m0 = mn0;
        m1 = mn1;

        // Rescale O, stash P (tf32) in warp-private smem band
        #pragma unroll
        for (int nt = 0; nt < 8; nt++) {
            o[nt][0] *= al0; o[nt][1] *= al0;
            o[nt][2] *= al1; o[nt][3] *= al1;
            uint2 p0 = {f2tf32(s[nt][0]), f2tf32(s[nt][1])};
            uint2 p1 = {f2tf32(s[nt][2]), f2tf32(s[nt][3])};
            *(uint2*)&Ps[(mbase + quad) * ALD + nt * 8 + 2 * tig] = p0;
            *(uint2*)&Ps[(mbase + quad + 8) * ALD + nt * 8 + 2 * tig] = p1;
        }
        __syncwarp();

        // O += P @ V  (P via LDSM, V scalar)
        #pragma unroll
        for (int kb = 0; kb < 64; kb += 8) {
            unsigned a0, a1, a2, a3;
            ldsm_x4(a0, a1, a2, a3, &Ps[(mbase + arow) * ALD + kb + acol]);
            #pragma unroll
            for (int nt = 0; nt < 8; nt++) {
                const unsigned b0 = Vc[(kb + tig) * VLD + nt * 8 + quad];
                const unsigned b1 = Vc[(kb + tig + 4) * VLD + nt * 8 + quad];
                mma_tf32(o[nt][0], o[nt][1], o[nt][2], o[nt][3],
                         a0, a1, a2, a3, b0, b1);
            }
        }

        if (jb < jmax) CP_WAIT0();
        __syncthreads();
        buf ^= 1;
    }

    // Normalize + write
    const float i0 = 1.0f / l0;
    const float i1 = 1.0f / l1;
    const size_t nrow0 = (size_t)bb * SEQ + qb * 128 + mbase + quad;
    #pragma unroll
    for (int nt = 0; nt < 8; nt++) {
        const int c = qcol + nt * 8 + 2 * tig;
        float2 w0 = {o[nt][0] * i0, o[nt][1] * i0};
        float2 w1 = {o[nt][2] * i1, o[nt][3] * i1};
        *(float2*)&g_att[nrow0 * INNER + c] = w0;
        *(float2*)&g_att[(nrow0 + 8) * INNER + c] = w1;
    }
}

// ---------------------------------------------------------------------------
extern "C" void kernel_launch(void* const* d_in, const int* in_sizes, int n_in,
                              void* d_out, int out_size)
{
    const float* x     = (const float*)d_in[0];  // [4,2048,1024]
    const float* w_qkv = (const float*)d_in[1];  // [1024,3072]
    const float* w_out = (const float*)d_in[2];  // [1024,1024]
    const float* b_out = (const float*)d_in[3];  // [1024]
    float* out = (float*)d_out;                  // [4,2048,1024]

    float* qkv_ptr = nullptr;
    float* att_ptr = nullptr;
    cudaGetSymbolAddress((void**)&qkv_ptr, g_qkv);
    cudaGetSymbolAddress((void**)&att_ptr, g_att);

    // 1) QKV projection (tf32 mma + ldmatrix); epilogue rounds to tf32
    {
        dim3 grid(QKV_COLS / 128, M_TOTAL / 128);   // (24, 64)
        tgemm128<false, true><<<grid, 256>>>(x, w_qkv, nullptr, qkv_ptr,
                                             M_TOTAL, QKV_COLS, DIM);
    }

    // 2) Causal flash attention (tf32 mma + ldmatrix, cp.async K/V pipeline)
    {
        const int smem_words = 128 * ALD * 2 + 2 * (64 * ALD + 64 * VLD);
        const int smem_bytes = smem_words * 4;      // 141312
        cudaFuncSetAttribute(attn_mma_kernel,
                             cudaFuncAttributeMaxDynamicSharedMemorySize,
                             smem_bytes);
        dim3 grid(SEQ / 128, BATCH * HEADS);        // (16, 64)
        attn_mma_kernel<<<grid, 256, smem_bytes>>>();
    }

    // 3) Output projection with bias (tf32 mma + ldmatrix, fp32 output)
    {
        dim3 grid(DIM / 128, M_TOTAL / 128);        // (8, 64)
        tgemm128<true, false><<<grid, 256>>>(att_ptr, w_out, b_out, out,
                                             M_TOTAL, DIM, INNER);
    }
}